// round 1
// baseline (speedup 1.0000x reference)
#include <cuda_runtime.h>
#include <math.h>

// ---------------------------------------------------------------------------
// QuantumFourierNeuralOperator
// B=16, H=W=128, Cin=3, WIDTH=64, MODES=16, SCHMIDT=8, N_LAYERS=4
//
// Restructured:
//   - Schmidt sum pre-folded into weights (8x less einsum work)
//   - truncated fft2 -> two DFT GEMM stages (F: 16x128)
//   - spectral einsum -> one real GEMM 256 x 2048 x 2048 per layer
//     (complex embedded: [Xr|Xi] * [[Wr,Wi],[-Wi,Wr]] = [Or|Oi])
//   - ifft2 stage 1 -> small complex GEMM (K=16)
//   - ifft2 stage 2 + pointwise (h@ww+wb) + gelu fused, in-place on h
//   - fc1 + gelu + fc2 fused
// ---------------------------------------------------------------------------

__device__ float g_h [16UL*128*128*64];   // activations (b,h,w,c)      67 MB
__device__ float g_W2[4UL*2048*2048];     // embedded spectral weights  67 MB
__device__ float g_Yr[16UL*16*128*64];    // (b,k1,w,c)
__device__ float g_Yi[16UL*16*128*64];
__device__ float g_X2[256UL*2048];        // (b*16+k1, [Xr|Xi])
__device__ float g_O [256UL*2048];        // (b*16+k1, [Or|Oi])
__device__ float g_Tr[16UL*128*16*64];    // (b,h,m,o)
__device__ float g_Ti[16UL*128*16*64];
__device__ float g_Fr[2048];              // [h][k] exp(-2pi i h k/128)
__device__ float g_Fi[2048];
__device__ float g_Gr[2048];              // [h][k] exp(+2pi i h k/128)/128
__device__ float g_Gi[2048];

__device__ __forceinline__ float gelu_f(float x) {
    float u = 0.7978845608028654f * (x + 0.044715f * x * x * x);
    return 0.5f * x * (1.0f + tanhf(u));
}

// ---------------------------------------------------------------------------
__global__ void twiddle_kernel() {
    int i = blockIdx.x * 256 + threadIdx.x;
    if (i >= 2048) return;
    int h = i >> 4, k = i & 15;
    float a = (float)(h * k) * (-1.0f / 64.0f);   // theta/pi for exp(-2pi i hk/128)
    float s, c;
    sincospif(a, &s, &c);
    g_Fr[i] = c;  g_Fi[i] = s;
    sincospif(-a, &s, &c);
    g_Gr[i] = c * (1.0f / 128.0f);
    g_Gi[i] = s * (1.0f / 128.0f);
}

// ---------------------------------------------------------------------------
// Pre-sum Schmidt rank + build complex-embedded 2048x2048 weight per layer.
// i enumerates (l,m,n,c,o); source wr/wi laid out [l][m][n][c][o][s], s=8.
__global__ void presum_kernel(const float* __restrict__ wr,
                              const float* __restrict__ wi) {
    int i = blockIdx.x * 256 + threadIdx.x;           // 4,194,304 total
    int o = i & 63;
    int c = (i >> 6) & 63;
    int n = (i >> 12) & 15;
    int m = (i >> 16) & 15;
    int l = i >> 20;
    size_t src = (size_t)i * 8;
    const float4* a4 = (const float4*)(wr + src);
    const float4* b4 = (const float4*)(wi + src);
    float4 a0 = a4[0], a1 = a4[1];
    float4 b0 = b4[0], b1 = b4[1];
    float sr = a0.x + a0.y + a0.z + a0.w + a1.x + a1.y + a1.z + a1.w;
    float si = b0.x + b0.y + b0.z + b0.w + b1.x + b1.y + b1.z + b1.w;
    const float INV = 0.35355339059327373f;           // 1/sqrt(8)
    sr *= INV;  si *= INV;
    size_t base = (size_t)l * (2048UL * 2048UL);
    int rc  = n * 64 + c;                             // K row (Xr part)
    int col = m * 64 + o;                             // N col (Or part)
    g_W2[base + (size_t)rc * 2048 + col]                  =  sr;
    g_W2[base + (size_t)rc * 2048 + 1024 + col]           =  si;
    g_W2[base + (size_t)(1024 + rc) * 2048 + col]         = -si;
    g_W2[base + (size_t)(1024 + rc) * 2048 + 1024 + col]  =  sr;
}

// ---------------------------------------------------------------------------
__global__ void fcin_kernel(const float* __restrict__ x,
                            const float* __restrict__ w,
                            const float* __restrict__ b) {
    size_t i = (size_t)blockIdx.x * 256 + threadIdx.x;   // 16,777,216
    int o = (int)(i & 63);
    size_t p = i >> 6;
    float x0 = x[p * 3], x1 = x[p * 3 + 1], x2 = x[p * 3 + 2];
    g_h[i] = x0 * w[o] + x1 * w[64 + o] + x2 * w[128 + o] + b[o];
}

// ---------------------------------------------------------------------------
// Stage A: DFT over H. Y[b,k1,w,c] = sum_h F[k1,h] * h[b,h,w,c]   (real input)
__global__ void __launch_bounds__(128) stageA_kernel() {
    __shared__ float Fr_s[2048], Fi_s[2048];
    int tid = threadIdx.x;
    int b = blockIdx.y;
    int col = blockIdx.x * 128 + tid;                 // w*64+c in [0,8192)
    for (int i = tid; i < 2048; i += 128) { Fr_s[i] = g_Fr[i]; Fi_s[i] = g_Fi[i]; }
    __syncthreads();
    float ar[16], ai[16];
#pragma unroll
    for (int k = 0; k < 16; k++) { ar[k] = 0.f; ai[k] = 0.f; }
    const float* hp = g_h + (size_t)b * 16384 * 64 + col;
#pragma unroll 4
    for (int hh = 0; hh < 128; hh++) {
        float v = hp[(size_t)hh * 8192];
        const float4* fr4 = (const float4*)(Fr_s + hh * 16);
        const float4* fi4 = (const float4*)(Fi_s + hh * 16);
#pragma unroll
        for (int kk = 0; kk < 4; kk++) {
            float4 fr = fr4[kk], fi = fi4[kk];
            ar[kk*4+0] += fr.x * v;  ai[kk*4+0] += fi.x * v;
            ar[kk*4+1] += fr.y * v;  ai[kk*4+1] += fi.y * v;
            ar[kk*4+2] += fr.z * v;  ai[kk*4+2] += fi.z * v;
            ar[kk*4+3] += fr.w * v;  ai[kk*4+3] += fi.w * v;
        }
    }
    size_t base = (size_t)b * 16 * 8192 + col;
#pragma unroll
    for (int k = 0; k < 16; k++) {
        g_Yr[base + (size_t)k * 8192] = ar[k];
        g_Yi[base + (size_t)k * 8192] = ai[k];
    }
}

// ---------------------------------------------------------------------------
// Stage B: DFT over W. X[b,k1,k2,c] = sum_w F[k2,w] * Y[b,k1,w,c]  (cplx*cplx)
// Writes embedded layout X2[(b*16+k1)][k2*64+c] (real) / +1024 (imag)
__global__ void __launch_bounds__(64) stageB_kernel() {
    __shared__ float Fr_s[2048], Fi_s[2048];
    int tid = threadIdx.x;                            // c
    int k1 = blockIdx.x, b = blockIdx.y;
    for (int i = tid; i < 2048; i += 64) { Fr_s[i] = g_Fr[i]; Fi_s[i] = g_Fi[i]; }
    __syncthreads();
    float xr[16], xi[16];
#pragma unroll
    for (int k = 0; k < 16; k++) { xr[k] = 0.f; xi[k] = 0.f; }
    size_t ybase = (size_t)(b * 16 + k1) * 8192 + tid;
#pragma unroll 2
    for (int w = 0; w < 128; w++) {
        float vr = g_Yr[ybase + w * 64];
        float vi = g_Yi[ybase + w * 64];
        const float4* fr4 = (const float4*)(Fr_s + w * 16);
        const float4* fi4 = (const float4*)(Fi_s + w * 16);
#pragma unroll
        for (int kk = 0; kk < 4; kk++) {
            float4 fr = fr4[kk], fi = fi4[kk];
            xr[kk*4+0] += fr.x * vr - fi.x * vi;  xi[kk*4+0] += fr.x * vi + fi.x * vr;
            xr[kk*4+1] += fr.y * vr - fi.y * vi;  xi[kk*4+1] += fr.y * vi + fi.y * vr;
            xr[kk*4+2] += fr.z * vr - fi.z * vi;  xi[kk*4+2] += fr.z * vi + fi.z * vr;
            xr[kk*4+3] += fr.w * vr - fi.w * vi;  xi[kk*4+3] += fr.w * vi + fi.w * vr;
        }
    }
    float* dst = g_X2 + (size_t)(b * 16 + k1) * 2048;
#pragma unroll
    for (int k = 0; k < 16; k++) {
        dst[k * 64 + tid]        = xr[k];
        dst[1024 + k * 64 + tid] = xi[k];
    }
}

// ---------------------------------------------------------------------------
// Spectral einsum GEMM: O(256 x 2048) = X2(256 x 2048) * W2_l(2048 x 2048)
// BM=64 BN=64 BK=16, 256 threads, 4x4 micro-tile.
__global__ void __launch_bounds__(256) gemm_kernel(int layer) {
    __shared__ float As[16][68];
    __shared__ float Bs[16][64];
    const float* B = g_W2 + (size_t)layer * (2048UL * 2048UL);
    int tid = threadIdx.x;
    int cBase = blockIdx.x * 64;
    int rBase = blockIdx.y * 64;
    int tr = tid >> 4, tc = tid & 15;
    int aRow = tid >> 2;
    int aK4  = (tid & 3) * 4;
    int bK   = tid >> 4;
    int bC4  = (tid & 15) * 4;
    const float* Aptr = g_X2 + (size_t)(rBase + aRow) * 2048 + aK4;
    const float* Bptr = B + (size_t)bK * 2048 + cBase + bC4;
    float acc[4][4];
#pragma unroll
    for (int i = 0; i < 4; i++)
#pragma unroll
        for (int j = 0; j < 4; j++) acc[i][j] = 0.f;

    for (int kt = 0; kt < 128; kt++) {
        float4 av = *(const float4*)(Aptr + kt * 16);
        float4 bv = *(const float4*)(Bptr + (size_t)kt * 16 * 2048);
        As[aK4 + 0][aRow] = av.x;
        As[aK4 + 1][aRow] = av.y;
        As[aK4 + 2][aRow] = av.z;
        As[aK4 + 3][aRow] = av.w;
        *(float4*)&Bs[bK][bC4] = bv;
        __syncthreads();
#pragma unroll
        for (int k = 0; k < 16; k++) {
            float4 a = *(const float4*)&As[k][tr * 4];
            float4 b4 = *(const float4*)&Bs[k][tc * 4];
            acc[0][0] += a.x * b4.x; acc[0][1] += a.x * b4.y; acc[0][2] += a.x * b4.z; acc[0][3] += a.x * b4.w;
            acc[1][0] += a.y * b4.x; acc[1][1] += a.y * b4.y; acc[1][2] += a.y * b4.z; acc[1][3] += a.y * b4.w;
            acc[2][0] += a.z * b4.x; acc[2][1] += a.z * b4.y; acc[2][2] += a.z * b4.z; acc[2][3] += a.z * b4.w;
            acc[3][0] += a.w * b4.x; acc[3][1] += a.w * b4.y; acc[3][2] += a.w * b4.z; acc[3][3] += a.w * b4.w;
        }
        __syncthreads();
    }
#pragma unroll
    for (int i = 0; i < 4; i++) {
        float* Cp = g_O + (size_t)(rBase + tr * 4 + i) * 2048 + cBase + tc * 4;
        *(float4*)Cp = make_float4(acc[i][0], acc[i][1], acc[i][2], acc[i][3]);
    }
}

// ---------------------------------------------------------------------------
// Stage C: inverse DFT over H-modes (K=16).
// T[b,h,m,o] = sum_x G[h,x] * O[(b,x)][m,o]   (cplx*cplx)
__global__ void stageC_kernel() {
    int i = blockIdx.x * 256 + threadIdx.x;           // 2,097,152
    int o  = i & 63;
    int m  = (i >> 6) & 15;
    int hh = (i >> 10) & 127;
    int b  = i >> 17;
    const float* Gr = g_Gr + hh * 16;
    const float* Gi = g_Gi + hh * 16;
    const float* Op = g_O + (size_t)b * 16 * 2048 + m * 64 + o;
    float tr = 0.f, ti = 0.f;
#pragma unroll
    for (int x = 0; x < 16; x++) {
        float gr = Gr[x], gi = Gi[x];
        float orr = Op[(size_t)x * 2048];
        float oii = Op[(size_t)x * 2048 + 1024];
        tr += gr * orr - gi * oii;
        ti += gr * oii + gi * orr;
    }
    g_Tr[i] = tr;
    g_Ti[i] = ti;
}

// ---------------------------------------------------------------------------
// Stage D (fused): x1[b,h,w,o] = Re(sum_m G[w,m]*T[b,h,m,o]);
//                  x2 = h @ ww + wb;   h = gelu(x1 + x2)  (in-place)
// CTA per (h,b). 2 phases of 64 w each to keep smem under 48KB.
__global__ void __launch_bounds__(256) stageD_kernel(const float* __restrict__ ww,
                                                     const float* __restrict__ wb) {
    __shared__ float Trs[1024], Tis[1024];
    __shared__ float wws[4096];
    __shared__ float hrow[64 * 68];
    int tid = threadIdx.x;
    int hh = blockIdx.x, b = blockIdx.y;
    size_t tbase = (size_t)(b * 128 + hh) * 1024;
    {
        const float4* tr4 = (const float4*)(g_Tr + tbase);
        const float4* ti4 = (const float4*)(g_Ti + tbase);
        if (tid < 256) {            // 256 float4 each
            ((float4*)Trs)[tid] = tr4[tid];
            ((float4*)Tis)[tid] = ti4[tid];
        }
        const float4* w4 = (const float4*)ww;
        for (int i4 = tid; i4 < 1024; i4 += 256)
            ((float4*)wws)[i4] = w4[i4];
    }
    int whalf = tid >> 2;                 // [0,64)
    int o0 = (tid & 3) * 16;              // o quarter
    size_t rowbase = (size_t)(b * 128 + hh) * 8192;

    for (int ph = 0; ph < 2; ph++) {
        __syncthreads();                  // previous phase readers done
        const float4* hp4 = (const float4*)(g_h + rowbase + (size_t)ph * 4096);
        for (int i4 = tid; i4 < 1024; i4 += 256) {
            int base = i4 * 4;
            int wl = base >> 6, c = base & 63;
            *(float4*)&hrow[wl * 68 + c] = hp4[i4];
        }
        __syncthreads();

        int w = ph * 64 + whalf;
        float Grw[16], Giw[16];
#pragma unroll
        for (int mm = 0; mm < 16; mm++) {
            Grw[mm] = g_Gr[w * 16 + mm];
            Giw[mm] = g_Gi[w * 16 + mm];
        }
        float acc[16];
#pragma unroll
        for (int j = 0; j < 16; j++) acc[j] = wb[o0 + j];
        // spectral part
#pragma unroll
        for (int mm = 0; mm < 16; mm++) {
            float gr = Grw[mm], gi = Giw[mm];
#pragma unroll
            for (int j4 = 0; j4 < 4; j4++) {
                float4 t_r = *(const float4*)&Trs[mm * 64 + o0 + j4 * 4];
                float4 t_i = *(const float4*)&Tis[mm * 64 + o0 + j4 * 4];
                acc[j4*4+0] += gr * t_r.x - gi * t_i.x;
                acc[j4*4+1] += gr * t_r.y - gi * t_i.y;
                acc[j4*4+2] += gr * t_r.z - gi * t_i.z;
                acc[j4*4+3] += gr * t_r.w - gi * t_i.w;
            }
        }
        // pointwise part
#pragma unroll 8
        for (int c = 0; c < 64; c++) {
            float hv = hrow[whalf * 68 + c];
#pragma unroll
            for (int j4 = 0; j4 < 4; j4++) {
                float4 wv = *(const float4*)&wws[c * 64 + o0 + j4 * 4];
                acc[j4*4+0] += hv * wv.x;
                acc[j4*4+1] += hv * wv.y;
                acc[j4*4+2] += hv * wv.z;
                acc[j4*4+3] += hv * wv.w;
            }
        }
        float* dst = g_h + rowbase + (size_t)w * 64 + o0;
#pragma unroll
        for (int j4 = 0; j4 < 4; j4++) {
            float4 r;
            r.x = gelu_f(acc[j4*4+0]);
            r.y = gelu_f(acc[j4*4+1]);
            r.z = gelu_f(acc[j4*4+2]);
            r.w = gelu_f(acc[j4*4+3]);
            *(float4*)&dst[j4 * 4] = r;
        }
    }
}

// ---------------------------------------------------------------------------
// Fused head: out[p] = gelu(h[p,:] @ w1 + b1) @ w2 + b2
// CTA: 128 threads, 32 pixels; thread = (pixel, j-quarter of 32).
__global__ void __launch_bounds__(128) fc12_kernel(const float* __restrict__ w1,
                                                   const float* __restrict__ b1,
                                                   const float* __restrict__ w2,
                                                   const float* __restrict__ b2,
                                                   float* __restrict__ out) {
    __shared__ float hs[32 * 68];
    __shared__ float w1s[64 * 128];
    __shared__ float w2s[128], b1s[128];
    int tid = threadIdx.x;
    size_t p0 = (size_t)blockIdx.x * 32;
    const float4* hp4 = (const float4*)(g_h + p0 * 64);
    for (int i4 = tid; i4 < 512; i4 += 128) {
        int base = i4 * 4;
        int p = base >> 6, c = base & 63;
        *(float4*)&hs[p * 68 + c] = hp4[i4];
    }
    const float4* w14 = (const float4*)w1;
    for (int i4 = tid; i4 < 2048; i4 += 128)
        ((float4*)w1s)[i4] = w14[i4];
    if (tid < 128) { w2s[tid] = w2[tid]; b1s[tid] = b1[tid]; }
    __syncthreads();

    int p = tid >> 2, jg = tid & 3, j0 = jg * 32;
    float acc[32];
#pragma unroll
    for (int j = 0; j < 32; j++) acc[j] = b1s[j0 + j];
#pragma unroll 4
    for (int c = 0; c < 64; c++) {
        float hv = hs[p * 68 + c];
#pragma unroll
        for (int j4 = 0; j4 < 8; j4++) {
            float4 wv = *(const float4*)&w1s[c * 128 + j0 + j4 * 4];
            acc[j4*4+0] += hv * wv.x;
            acc[j4*4+1] += hv * wv.y;
            acc[j4*4+2] += hv * wv.z;
            acc[j4*4+3] += hv * wv.w;
        }
    }
    float s = 0.f;
#pragma unroll
    for (int j = 0; j < 32; j++) s += gelu_f(acc[j]) * w2s[j0 + j];
    s += __shfl_xor_sync(0xffffffffu, s, 1);
    s += __shfl_xor_sync(0xffffffffu, s, 2);
    if (jg == 0) out[p0 + p] = s + b2[0];
}

// ---------------------------------------------------------------------------
extern "C" void kernel_launch(void* const* d_in, const int* in_sizes, int n_in,
                              void* d_out, int out_size) {
    const float* x       = (const float*)d_in[0];
    const float* fc_in_w = (const float*)d_in[1];
    const float* fc_in_b = (const float*)d_in[2];
    const float* wr      = (const float*)d_in[3];
    const float* wi      = (const float*)d_in[4];
    const float* ww      = (const float*)d_in[5];
    const float* wb      = (const float*)d_in[6];
    const float* fc1_w   = (const float*)d_in[7];
    const float* fc1_b   = (const float*)d_in[8];
    const float* fc2_w   = (const float*)d_in[9];
    const float* fc2_b   = (const float*)d_in[10];
    float* out = (float*)d_out;

    twiddle_kernel<<<8, 256>>>();
    presum_kernel<<<16384, 256>>>(wr, wi);
    fcin_kernel<<<65536, 256>>>(x, fc_in_w, fc_in_b);

    for (int l = 0; l < 4; l++) {
        stageA_kernel<<<dim3(64, 16), 128>>>();
        stageB_kernel<<<dim3(16, 16), 64>>>();
        gemm_kernel<<<dim3(32, 4), 256>>>(l);
        stageC_kernel<<<8192, 256>>>();
        stageD_kernel<<<dim3(128, 16), 256>>>(ww + (size_t)l * 4096,
                                              wb + (size_t)l * 64);
    }
    fc12_kernel<<<8192, 128>>>(fc1_w, fc1_b, fc2_w, fc2_b, out);
}

// round 2
// speedup vs baseline: 1.8253x; 1.8253x over previous
#include <cuda_runtime.h>
#include <math.h>

// ---------------------------------------------------------------------------
// QuantumFourierNeuralOperator  (B=16, H=W=128, Cin=3, WIDTH=64, MODES=16,
// SCHMIDT=8, N_LAYERS=4)
//
// R2: split-K gemm (full-chip), vectorized stageA, 2x-threads stageB,
//     register-blocked stageD, 2-pixel fc12.
// ---------------------------------------------------------------------------

__device__ float g_h [16UL*128*128*64];   // activations (b,h,w,c)      67 MB
__device__ float g_W2[4UL*2048*2048];     // embedded spectral weights  67 MB
__device__ float g_Yr[16UL*16*128*64];    // (b,k1,w,c)
__device__ float g_Yi[16UL*16*128*64];
__device__ float g_X2[256UL*2048];        // (b*16+k1, [Xr|Xi])
__device__ float g_O [256UL*2048];        // (b*16+k1, [Or|Oi])
__device__ float g_Op[8UL*256*2048];      // split-K partials
__device__ float g_Tr[16UL*128*16*64];    // (b,h,m,o)
__device__ float g_Ti[16UL*128*16*64];
__device__ float g_Fr[2048];              // [h][k] exp(-2pi i h k/128)
__device__ float g_Fi[2048];
__device__ float g_Gr[2048];              // [h][k] exp(+2pi i h k/128)/128
__device__ float g_Gi[2048];

__device__ __forceinline__ float gelu_f(float x) {
    float u = 0.7978845608028654f * (x + 0.044715f * x * x * x);
    return 0.5f * x * (1.0f + tanhf(u));
}

// ---------------------------------------------------------------------------
__global__ void twiddle_kernel() {
    int i = blockIdx.x * 256 + threadIdx.x;
    if (i >= 2048) return;
    int h = i >> 4, k = i & 15;
    float a = (float)(h * k) * (-1.0f / 64.0f);
    float s, c;
    sincospif(a, &s, &c);
    g_Fr[i] = c;  g_Fi[i] = s;
    sincospif(-a, &s, &c);
    g_Gr[i] = c * (1.0f / 128.0f);
    g_Gi[i] = s * (1.0f / 128.0f);
}

// ---------------------------------------------------------------------------
// Pre-sum Schmidt rank + build complex-embedded 2048x2048 weight per layer.
__global__ void presum_kernel(const float* __restrict__ wr,
                              const float* __restrict__ wi) {
    int i = blockIdx.x * 256 + threadIdx.x;           // 4,194,304 total
    int o = i & 63;
    int c = (i >> 6) & 63;
    int n = (i >> 12) & 15;
    int m = (i >> 16) & 15;
    int l = i >> 20;
    size_t src = (size_t)i * 8;
    const float4* a4 = (const float4*)(wr + src);
    const float4* b4 = (const float4*)(wi + src);
    float4 a0 = a4[0], a1 = a4[1];
    float4 b0 = b4[0], b1 = b4[1];
    float sr = a0.x + a0.y + a0.z + a0.w + a1.x + a1.y + a1.z + a1.w;
    float si = b0.x + b0.y + b0.z + b0.w + b1.x + b1.y + b1.z + b1.w;
    const float INV = 0.35355339059327373f;           // 1/sqrt(8)
    sr *= INV;  si *= INV;
    size_t base = (size_t)l * (2048UL * 2048UL);
    int rc  = n * 64 + c;
    int col = m * 64 + o;
    g_W2[base + (size_t)rc * 2048 + col]                  =  sr;
    g_W2[base + (size_t)rc * 2048 + 1024 + col]           =  si;
    g_W2[base + (size_t)(1024 + rc) * 2048 + col]         = -si;
    g_W2[base + (size_t)(1024 + rc) * 2048 + 1024 + col]  =  sr;
}

// ---------------------------------------------------------------------------
__global__ void fcin_kernel(const float* __restrict__ x,
                            const float* __restrict__ w,
                            const float* __restrict__ b) {
    size_t i = (size_t)blockIdx.x * 256 + threadIdx.x;   // 16,777,216
    int o = (int)(i & 63);
    size_t p = i >> 6;
    float x0 = x[p * 3], x1 = x[p * 3 + 1], x2 = x[p * 3 + 2];
    g_h[i] = x0 * w[o] + x1 * w[64 + o] + x2 * w[128 + o] + b[o];
}

// ---------------------------------------------------------------------------
// Stage A: DFT over H. Y[b,k1,w,c] = sum_h F[k1,h]*h[b,h,w,c]  (real input)
// Thread: 4 cols (float4) x 4 k-modes.  grid (32,16) x 256.
__global__ void __launch_bounds__(256) stageA_kernel() {
    __shared__ float Fr_s[2048], Fi_s[2048];
    int tid = threadIdx.x;
    int b = blockIdx.y;
    int cq = tid & 63;
    int kh = tid >> 6;                 // 0..3
    int k0 = kh * 4;
    int col = blockIdx.x * 256 + cq * 4;
    for (int i = tid; i < 512; i += 256) {
        ((float4*)Fr_s)[i] = ((const float4*)g_Fr)[i];
        ((float4*)Fi_s)[i] = ((const float4*)g_Fi)[i];
    }
    __syncthreads();
    float ar[4][4], ai[4][4];
#pragma unroll
    for (int k = 0; k < 4; k++)
#pragma unroll
        for (int j = 0; j < 4; j++) { ar[k][j] = 0.f; ai[k][j] = 0.f; }

    const float* hp = g_h + (size_t)b * 1048576 + col;
#pragma unroll 4
    for (int hh = 0; hh < 128; hh++) {
        float4 v  = *(const float4*)(hp + (size_t)hh * 8192);
        float4 fr = *(const float4*)(Fr_s + hh * 16 + k0);
        float4 fi = *(const float4*)(Fi_s + hh * 16 + k0);
        const float* frp = (const float*)&fr;
        const float* fip = (const float*)&fi;
#pragma unroll
        for (int k = 0; k < 4; k++) {
            float f0 = frp[k], f1 = fip[k];
            ar[k][0] += f0 * v.x;  ai[k][0] += f1 * v.x;
            ar[k][1] += f0 * v.y;  ai[k][1] += f1 * v.y;
            ar[k][2] += f0 * v.z;  ai[k][2] += f1 * v.z;
            ar[k][3] += f0 * v.w;  ai[k][3] += f1 * v.w;
        }
    }
    size_t base = (size_t)b * 131072 + col;
#pragma unroll
    for (int k = 0; k < 4; k++) {
        *(float4*)(g_Yr + base + (size_t)(k0 + k) * 8192) =
            make_float4(ar[k][0], ar[k][1], ar[k][2], ar[k][3]);
        *(float4*)(g_Yi + base + (size_t)(k0 + k) * 8192) =
            make_float4(ai[k][0], ai[k][1], ai[k][2], ai[k][3]);
    }
}

// ---------------------------------------------------------------------------
// Stage B: DFT over W. X[b,k1,k2,c] = sum_w F[k2,w]*Y[b,k1,w,c] (cplx*cplx)
// Thread: 1 c x 8 k2.  block 128 = 64 c x 2 k2-halves.  grid (16,16).
__global__ void __launch_bounds__(128) stageB_kernel() {
    __shared__ float Fr_s[2048], Fi_s[2048];
    int tid = threadIdx.x;
    int c   = tid & 63;
    int k2h = tid >> 6;                  // 0..1
    int k1 = blockIdx.x, b = blockIdx.y;
    for (int i = tid; i < 512; i += 128) {
        ((float4*)Fr_s)[i] = ((const float4*)g_Fr)[i];
        ((float4*)Fi_s)[i] = ((const float4*)g_Fi)[i];
    }
    __syncthreads();
    float xr[8], xi[8];
#pragma unroll
    for (int k = 0; k < 8; k++) { xr[k] = 0.f; xi[k] = 0.f; }
    size_t ybase = (size_t)(b * 16 + k1) * 8192 + c;
#pragma unroll 2
    for (int w = 0; w < 128; w++) {
        float vr = g_Yr[ybase + w * 64];
        float vi = g_Yi[ybase + w * 64];
        float4 fra = *(const float4*)(Fr_s + w * 16 + k2h * 8);
        float4 frb = *(const float4*)(Fr_s + w * 16 + k2h * 8 + 4);
        float4 fia = *(const float4*)(Fi_s + w * 16 + k2h * 8);
        float4 fib = *(const float4*)(Fi_s + w * 16 + k2h * 8 + 4);
        const float* fr = (const float*)&fra;   // fra,frb contiguous? no — index separately
        const float* fi = (const float*)&fia;
#pragma unroll
        for (int k = 0; k < 4; k++) {
            xr[k] += fr[k] * vr - fi[k] * vi;
            xi[k] += fr[k] * vi + fi[k] * vr;
        }
        const float* fr2 = (const float*)&frb;
        const float* fi2 = (const float*)&fib;
#pragma unroll
        for (int k = 0; k < 4; k++) {
            xr[4 + k] += fr2[k] * vr - fi2[k] * vi;
            xi[4 + k] += fr2[k] * vi + fi2[k] * vr;
        }
    }
    float* dst = g_X2 + (size_t)(b * 16 + k1) * 2048;
#pragma unroll
    for (int k = 0; k < 8; k++) {
        dst[(k2h * 8 + k) * 64 + c]        = xr[k];
        dst[1024 + (k2h * 8 + k) * 64 + c] = xi[k];
    }
}

// ---------------------------------------------------------------------------
// Spectral einsum GEMM, split-K: Op[kz] = X2[:, kz*256:+256] * W2[kz*256:+256,:]
// BM=64 BN=64 BK=16, 256 threads, 4x4 micro-tile. grid (32, 4, 8).
__global__ void __launch_bounds__(256) gemm_kernel(int layer) {
    __shared__ float As[16][68];
    __shared__ float Bs[16][64];
    const float* B = g_W2 + (size_t)layer * (2048UL * 2048UL);
    int tid = threadIdx.x;
    int cBase = blockIdx.x * 64;
    int rBase = blockIdx.y * 64;
    int kz    = blockIdx.z;
    int tr = tid >> 4, tc = tid & 15;
    int aRow = tid >> 2;
    int aK4  = (tid & 3) * 4;
    int bK   = tid >> 4;
    int bC4  = (tid & 15) * 4;
    const float* Aptr = g_X2 + (size_t)(rBase + aRow) * 2048 + kz * 256 + aK4;
    const float* Bptr = B + (size_t)(kz * 256 + bK) * 2048 + cBase + bC4;
    float acc[4][4];
#pragma unroll
    for (int i = 0; i < 4; i++)
#pragma unroll
        for (int j = 0; j < 4; j++) acc[i][j] = 0.f;

#pragma unroll 2
    for (int kt = 0; kt < 16; kt++) {
        float4 av = *(const float4*)(Aptr + kt * 16);
        float4 bv = *(const float4*)(Bptr + (size_t)kt * 16 * 2048);
        As[aK4 + 0][aRow] = av.x;
        As[aK4 + 1][aRow] = av.y;
        As[aK4 + 2][aRow] = av.z;
        As[aK4 + 3][aRow] = av.w;
        *(float4*)&Bs[bK][bC4] = bv;
        __syncthreads();
#pragma unroll
        for (int k = 0; k < 16; k++) {
            float4 a  = *(const float4*)&As[k][tr * 4];
            float4 b4 = *(const float4*)&Bs[k][tc * 4];
            acc[0][0] += a.x * b4.x; acc[0][1] += a.x * b4.y; acc[0][2] += a.x * b4.z; acc[0][3] += a.x * b4.w;
            acc[1][0] += a.y * b4.x; acc[1][1] += a.y * b4.y; acc[1][2] += a.y * b4.z; acc[1][3] += a.y * b4.w;
            acc[2][0] += a.z * b4.x; acc[2][1] += a.z * b4.y; acc[2][2] += a.z * b4.z; acc[2][3] += a.z * b4.w;
            acc[3][0] += a.w * b4.x; acc[3][1] += a.w * b4.y; acc[3][2] += a.w * b4.z; acc[3][3] += a.w * b4.w;
        }
        __syncthreads();
    }
#pragma unroll
    for (int i = 0; i < 4; i++) {
        float* Cp = g_Op + (size_t)kz * 524288 +
                    (size_t)(rBase + tr * 4 + i) * 2048 + cBase + tc * 4;
        *(float4*)Cp = make_float4(acc[i][0], acc[i][1], acc[i][2], acc[i][3]);
    }
}

// Sum 8 split-K partials.  grid 512 x 256 (float4).
__global__ void reduceO_kernel() {
    int i4 = blockIdx.x * 256 + threadIdx.x;     // < 131072
    float4 a = ((const float4*)g_Op)[i4];
#pragma unroll
    for (int s = 1; s < 8; s++) {
        float4 b = ((const float4*)g_Op)[s * 131072 + i4];
        a.x += b.x; a.y += b.y; a.z += b.z; a.w += b.w;
    }
    ((float4*)g_O)[i4] = a;
}

// ---------------------------------------------------------------------------
// Stage C: inverse DFT over H-modes (K=16).
__global__ void stageC_kernel() {
    int i = blockIdx.x * 256 + threadIdx.x;           // 2,097,152
    int o  = i & 63;
    int m  = (i >> 6) & 15;
    int hh = (i >> 10) & 127;
    int b  = i >> 17;
    const float* Gr = g_Gr + hh * 16;
    const float* Gi = g_Gi + hh * 16;
    const float* Op = g_O + (size_t)b * 16 * 2048 + m * 64 + o;
    float tr = 0.f, ti = 0.f;
#pragma unroll
    for (int x = 0; x < 16; x++) {
        float gr = Gr[x], gi = Gi[x];
        float orr = Op[(size_t)x * 2048];
        float oii = Op[(size_t)x * 2048 + 1024];
        tr += gr * orr - gi * oii;
        ti += gr * oii + gi * orr;
    }
    g_Tr[i] = tr;
    g_Ti[i] = ti;
}

// ---------------------------------------------------------------------------
// Stage D (fused): x1 = Re(iDFT_W of T); x2 = h@ww+wb; h = gelu(x1+x2).
// CTA per (h,b), 128 threads; thread = 4 w x 16 o register tile.
__global__ void __launch_bounds__(128) stageD_kernel(const float* __restrict__ ww,
                                                     const float* __restrict__ wb) {
    __shared__ float Trs[1024], Tis[1024];
    __shared__ float wwt[1024];              // 16c x 64o tile
    __shared__ float hrow[128 * 68];         // 34816 B
    int tid = threadIdx.x;
    int hh = blockIdx.x, b = blockIdx.y;
    int wq = tid >> 2;          // 0..31
    int w0 = wq * 4;
    int og = tid & 3;
    int o0 = og * 16;
    size_t tbase = (size_t)(b * 128 + hh) * 1024;
    size_t rowbase = (size_t)(b * 128 + hh) * 8192;

    for (int i = tid; i < 256; i += 128) {
        ((float4*)Trs)[i] = ((const float4*)(g_Tr + tbase))[i];
        ((float4*)Tis)[i] = ((const float4*)(g_Ti + tbase))[i];
    }
    for (int i4 = tid; i4 < 2048; i4 += 128) {
        int base = i4 * 4;
        int wl = base >> 6, cc = base & 63;
        *(float4*)&hrow[wl * 68 + cc] = ((const float4*)(g_h + rowbase))[i4];
    }
    __syncthreads();

    float acc[4][16];
#pragma unroll
    for (int dw = 0; dw < 4; dw++)
#pragma unroll
        for (int j = 0; j < 16; j++) acc[dw][j] = wb[o0 + j];

    // ---- spectral: acc += Re( G[w,:] . T[:, o] )
#pragma unroll
    for (int mq = 0; mq < 4; mq++) {
        float4 Gr4[4], Gi4[4];
#pragma unroll
        for (int dw = 0; dw < 4; dw++) {
            Gr4[dw] = *(const float4*)(g_Gr + (w0 + dw) * 16 + mq * 4);
            Gi4[dw] = *(const float4*)(g_Gi + (w0 + dw) * 16 + mq * 4);
        }
#pragma unroll
        for (int mm = 0; mm < 4; mm++) {
            int m = mq * 4 + mm;
            float4 t_r[4], t_i[4];
#pragma unroll
            for (int j4 = 0; j4 < 4; j4++) {
                t_r[j4] = *(const float4*)&Trs[m * 64 + o0 + j4 * 4];
                t_i[j4] = *(const float4*)&Tis[m * 64 + o0 + j4 * 4];
            }
#pragma unroll
            for (int dw = 0; dw < 4; dw++) {
                float gr = ((const float*)&Gr4[dw])[mm];
                float gi = ((const float*)&Gi4[dw])[mm];
#pragma unroll
                for (int j4 = 0; j4 < 4; j4++) {
                    acc[dw][j4*4+0] += gr * t_r[j4].x - gi * t_i[j4].x;
                    acc[dw][j4*4+1] += gr * t_r[j4].y - gi * t_i[j4].y;
                    acc[dw][j4*4+2] += gr * t_r[j4].z - gi * t_i[j4].z;
                    acc[dw][j4*4+3] += gr * t_r[j4].w - gi * t_i[j4].w;
                }
            }
        }
    }

    // ---- pointwise: acc += h[w,:] @ ww  (c tiled by 16)
    for (int ct = 0; ct < 4; ct++) {
        __syncthreads();
        for (int i = tid; i < 256; i += 128)
            ((float4*)wwt)[i] = ((const float4*)(ww + ct * 1024))[i];
        __syncthreads();
#pragma unroll
        for (int c = 0; c < 16; c++) {
            float hv[4];
#pragma unroll
            for (int dw = 0; dw < 4; dw++)
                hv[dw] = hrow[(w0 + dw) * 68 + ct * 16 + c];
#pragma unroll
            for (int j4 = 0; j4 < 4; j4++) {
                float4 wv = *(const float4*)&wwt[c * 64 + o0 + j4 * 4];
#pragma unroll
                for (int dw = 0; dw < 4; dw++) {
                    acc[dw][j4*4+0] += hv[dw] * wv.x;
                    acc[dw][j4*4+1] += hv[dw] * wv.y;
                    acc[dw][j4*4+2] += hv[dw] * wv.z;
                    acc[dw][j4*4+3] += hv[dw] * wv.w;
                }
            }
        }
    }

#pragma unroll
    for (int dw = 0; dw < 4; dw++) {
        float* dst = g_h + rowbase + (size_t)(w0 + dw) * 64 + o0;
#pragma unroll
        for (int j4 = 0; j4 < 4; j4++) {
            float4 r;
            r.x = gelu_f(acc[dw][j4*4+0]);
            r.y = gelu_f(acc[dw][j4*4+1]);
            r.z = gelu_f(acc[dw][j4*4+2]);
            r.w = gelu_f(acc[dw][j4*4+3]);
            *(float4*)&dst[j4 * 4] = r;
        }
    }
}

// ---------------------------------------------------------------------------
// Fused head: out = gelu(h @ w1 + b1) @ w2 + b2.
// CTA: 128 threads, 64 pixels; thread = 2 pixels x 32 j.  grid 4096.
__global__ void __launch_bounds__(128) fc12_kernel(const float* __restrict__ w1,
                                                   const float* __restrict__ b1,
                                                   const float* __restrict__ w2,
                                                   const float* __restrict__ b2,
                                                   float* __restrict__ out) {
    __shared__ float hs[64 * 64];     // [c][p]  16 KB
    __shared__ float w1s[64 * 128];   // 32 KB
    int tid = threadIdx.x;
    size_t p0 = (size_t)blockIdx.x * 64;
    const float4* hp4 = (const float4*)(g_h + p0 * 64);
    for (int i4 = tid; i4 < 1024; i4 += 128) {
        int base = i4 * 4;
        int p = base >> 6, c = base & 63;
        float4 v = hp4[i4];
        hs[(c + 0) * 64 + p] = v.x;
        hs[(c + 1) * 64 + p] = v.y;
        hs[(c + 2) * 64 + p] = v.z;
        hs[(c + 3) * 64 + p] = v.w;
    }
    const float4* w14 = (const float4*)w1;
    for (int i4 = tid; i4 < 2048; i4 += 128)
        ((float4*)w1s)[i4] = w14[i4];
    __syncthreads();

    int pp = tid >> 2, jg = tid & 3, j0 = jg * 32;
    float acc0[32], acc1[32];
#pragma unroll
    for (int j = 0; j < 32; j++) { acc0[j] = b1[j0 + j]; acc1[j] = acc0[j]; }
#pragma unroll 4
    for (int c = 0; c < 64; c++) {
        float h0 = hs[c * 64 + pp];
        float h1 = hs[c * 64 + pp + 32];
#pragma unroll
        for (int j4 = 0; j4 < 8; j4++) {
            float4 wv = *(const float4*)&w1s[c * 128 + j0 + j4 * 4];
            acc0[j4*4+0] += h0 * wv.x;  acc1[j4*4+0] += h1 * wv.x;
            acc0[j4*4+1] += h0 * wv.y;  acc1[j4*4+1] += h1 * wv.y;
            acc0[j4*4+2] += h0 * wv.z;  acc1[j4*4+2] += h1 * wv.z;
            acc0[j4*4+3] += h0 * wv.w;  acc1[j4*4+3] += h1 * wv.w;
        }
    }
    float s0 = 0.f, s1 = 0.f;
#pragma unroll
    for (int j = 0; j < 32; j++) {
        float w2v = w2[j0 + j];
        s0 += gelu_f(acc0[j]) * w2v;
        s1 += gelu_f(acc1[j]) * w2v;
    }
    s0 += __shfl_xor_sync(0xffffffffu, s0, 1);
    s0 += __shfl_xor_sync(0xffffffffu, s0, 2);
    s1 += __shfl_xor_sync(0xffffffffu, s1, 1);
    s1 += __shfl_xor_sync(0xffffffffu, s1, 2);
    if (jg == 0) {
        out[p0 + pp]      = s0 + b2[0];
        out[p0 + pp + 32] = s1 + b2[0];
    }
}

// ---------------------------------------------------------------------------
extern "C" void kernel_launch(void* const* d_in, const int* in_sizes, int n_in,
                              void* d_out, int out_size) {
    const float* x       = (const float*)d_in[0];
    const float* fc_in_w = (const float*)d_in[1];
    const float* fc_in_b = (const float*)d_in[2];
    const float* wr      = (const float*)d_in[3];
    const float* wi      = (const float*)d_in[4];
    const float* ww      = (const float*)d_in[5];
    const float* wb      = (const float*)d_in[6];
    const float* fc1_w   = (const float*)d_in[7];
    const float* fc1_b   = (const float*)d_in[8];
    const float* fc2_w   = (const float*)d_in[9];
    const float* fc2_b   = (const float*)d_in[10];
    float* out = (float*)d_out;

    twiddle_kernel<<<8, 256>>>();
    presum_kernel<<<16384, 256>>>(wr, wi);
    fcin_kernel<<<65536, 256>>>(x, fc_in_w, fc_in_b);

    for (int l = 0; l < 4; l++) {
        stageA_kernel<<<dim3(32, 16), 256>>>();
        stageB_kernel<<<dim3(16, 16), 128>>>();
        gemm_kernel<<<dim3(32, 4, 8), 256>>>(l);
        reduceO_kernel<<<512, 256>>>();
        stageC_kernel<<<8192, 256>>>();
        stageD_kernel<<<dim3(128, 16), 128>>>(ww + (size_t)l * 4096,
                                              wb + (size_t)l * 64);
    }
    fc12_kernel<<<4096, 128>>>(fc1_w, fc1_b, fc2_w, fc2_b, out);
}

// round 3
// speedup vs baseline: 3.8121x; 2.0884x over previous
#include <cuda_runtime.h>
#include <math.h>

// ---------------------------------------------------------------------------
// QuantumFourierNeuralOperator  (B=16, H=W=128, Cin=3, WIDTH=64, MODES=16,
// SCHMIDT=8, N_LAYERS=4)
//
// R3: tf32 mma.sync everywhere GEMM-shaped (stageA DFT, spectral einsum,
//     stageD iDFT+pointwise+gelu, fc1/fc2 head). Compact Wr/Wi weights.
// ---------------------------------------------------------------------------

__device__ float g_h [16UL*128*128*64];   // activations (b,h,w,c)      67 MB
__device__ float g_Wr[4UL*1024*1024];     // Schmidt-summed weights Re  16.8 MB
__device__ float g_Wi[4UL*1024*1024];     //                        Im  16.8 MB
__device__ float g_Y2[16UL*32*8192];      // stageA out: (b, 2k1|2k1+1, w*64+c)
__device__ float g_X2[256UL*2048];        // (b*16+k1, [Xr|Xi])
__device__ float g_O [256UL*2048];        // (b*16+k1, [Or|Oi])
__device__ float g_Op[8UL*256*2048];      // split-K partials
__device__ float g_TT[2048UL*32*64];      // (b*128+h, 2m:Tr/2m+1:-Ti, o)
__device__ float g_Fr[2048], g_Fi[2048];  // [h][k] exp(-2pi i hk/128)
__device__ float g_F2[32*128];            // [2k|2k+1][h] Re/Im of F (stageA A-op)
__device__ float g_Gr[2048], g_Gi[2048];  // [h][k] exp(+2pi i hk/128)/128
__device__ float g_G2[128*32];            // [w][2m|2m+1] Re/Im of G (stageD A-op)

__device__ __forceinline__ float gelu_f(float x) {
    float u = 0.7978845608028654f * (x + 0.044715f * x * x * x);
    return 0.5f * x * (1.0f + tanhf(u));
}

__device__ __forceinline__ unsigned f2tf(float x) {
    unsigned r;
    asm("cvt.rna.tf32.f32 %0, %1;" : "=r"(r) : "f"(x));
    return r;
}

__device__ __forceinline__ void mma_tf32(float* c, unsigned a0, unsigned a1,
                                         unsigned a2, unsigned a3,
                                         unsigned b0, unsigned b1) {
    asm volatile(
        "mma.sync.aligned.m16n8k8.row.col.f32.tf32.tf32.f32 "
        "{%0,%1,%2,%3}, {%4,%5,%6,%7}, {%8,%9}, {%0,%1,%2,%3};"
        : "+f"(c[0]), "+f"(c[1]), "+f"(c[2]), "+f"(c[3])
        : "r"(a0), "r"(a1), "r"(a2), "r"(a3), "r"(b0), "r"(b1));
}

// ---------------------------------------------------------------------------
__global__ void twiddle_kernel() {
    int i = blockIdx.x * 256 + threadIdx.x;
    if (i >= 2048) return;
    int h = i >> 4, k = i & 15;
    float a = (float)(h * k) * (-1.0f / 64.0f);
    float s, c;
    sincospif(a, &s, &c);
    g_Fr[i] = c;  g_Fi[i] = s;
    g_F2[(2 * k) * 128 + h]     = c;
    g_F2[(2 * k + 1) * 128 + h] = s;
    sincospif(-a, &s, &c);
    float gr = c * (1.0f / 128.0f);
    float gi = s * (1.0f / 128.0f);
    g_Gr[i] = gr;  g_Gi[i] = gi;
    g_G2[h * 32 + 2 * k]     = gr;
    g_G2[h * 32 + 2 * k + 1] = gi;
}

// ---------------------------------------------------------------------------
// Pre-sum Schmidt rank into compact Wr/Wi (rows = n*64+c, cols = m*64+o).
__global__ void presum_kernel(const float* __restrict__ wr,
                              const float* __restrict__ wi) {
    int i = blockIdx.x * 256 + threadIdx.x;           // 4,194,304 total
    int o = i & 63;
    int c = (i >> 6) & 63;
    int n = (i >> 12) & 15;
    int m = (i >> 16) & 15;
    int l = i >> 20;
    size_t src = (size_t)i * 8;
    const float4* a4 = (const float4*)(wr + src);
    const float4* b4 = (const float4*)(wi + src);
    float4 a0 = a4[0], a1 = a4[1];
    float4 b0 = b4[0], b1 = b4[1];
    float sr = a0.x + a0.y + a0.z + a0.w + a1.x + a1.y + a1.z + a1.w;
    float si = b0.x + b0.y + b0.z + b0.w + b1.x + b1.y + b1.z + b1.w;
    const float INV = 0.35355339059327373f;           // 1/sqrt(8)
    sr *= INV;  si *= INV;
    size_t dst = (size_t)l * 1048576 + (size_t)(n * 64 + c) * 1024 + m * 64 + o;
    g_Wr[dst] = sr;
    g_Wi[dst] = si;
}

// ---------------------------------------------------------------------------
__global__ void fcin_kernel(const float* __restrict__ x,
                            const float* __restrict__ w,
                            const float* __restrict__ b) {
    size_t i = (size_t)blockIdx.x * 256 + threadIdx.x;   // 16,777,216
    int o = (int)(i & 63);
    size_t p = i >> 6;
    float x0 = x[p * 3], x1 = x[p * 3 + 1], x2 = x[p * 3 + 2];
    g_h[i] = x0 * w[o] + x1 * w[64 + o] + x2 * w[128 + o] + b[o];
}

// ---------------------------------------------------------------------------
// Stage A (mma): Y2[b, 32 mode-rows, 8192 px] = F2(32x128) x h(128x8192).
// grid (32 colblk, 16 b), 128 threads. Per warp: M=32 (2 tiles) x N=64 (8 tiles).
__global__ void __launch_bounds__(128) stageA_mma() {
    int tid = threadIdx.x, warp = tid >> 5, lane = tid & 31;
    int gid = lane >> 2, tig = lane & 3;
    int b = blockIdx.y;
    int colbase = blockIdx.x * 256 + warp * 64;
    const float* hb = g_h + (size_t)b * 1048576;
    float acc[2][8][4];
#pragma unroll
    for (int m = 0; m < 2; m++)
#pragma unroll
        for (int n = 0; n < 8; n++)
#pragma unroll
            for (int j = 0; j < 4; j++) acc[m][n][j] = 0.f;

    for (int ks = 0; ks < 16; ks++) {
        int k0 = ks * 8;
        unsigned bf[8][2];
        const float* Bp = hb + (size_t)(k0 + tig) * 8192 + colbase + gid;
#pragma unroll
        for (int n = 0; n < 8; n++) {
            bf[n][0] = f2tf(Bp[n * 8]);
            bf[n][1] = f2tf(Bp[4 * 8192 + n * 8]);
        }
#pragma unroll
        for (int m = 0; m < 2; m++) {
            const float* Ap = g_F2 + (m * 16 + gid) * 128 + k0 + tig;
            unsigned a0 = f2tf(Ap[0]);
            unsigned a1 = f2tf(Ap[8 * 128]);
            unsigned a2 = f2tf(Ap[4]);
            unsigned a3 = f2tf(Ap[8 * 128 + 4]);
#pragma unroll
            for (int n = 0; n < 8; n++)
                mma_tf32(acc[m][n], a0, a1, a2, a3, bf[n][0], bf[n][1]);
        }
    }
    float* Yb = g_Y2 + (size_t)b * 262144;
#pragma unroll
    for (int m = 0; m < 2; m++)
#pragma unroll
        for (int n = 0; n < 8; n++) {
            int row = m * 16 + gid;
            int col = colbase + n * 8 + 2 * tig;
            *(float2*)(Yb + (size_t)row * 8192 + col) =
                make_float2(acc[m][n][0], acc[m][n][1]);
            *(float2*)(Yb + (size_t)(row + 8) * 8192 + col) =
                make_float2(acc[m][n][2], acc[m][n][3]);
        }
}

// ---------------------------------------------------------------------------
// Stage B: DFT over W. X[b,k1,k2,c] = sum_w F[k2,w]*Y[b,k1,w,c] (cplx*cplx)
__global__ void __launch_bounds__(128) stageB_kernel() {
    __shared__ float Fr_s[2048], Fi_s[2048];
    int tid = threadIdx.x;
    int c   = tid & 63;
    int k2h = tid >> 6;                  // 0..1
    int k1 = blockIdx.x, b = blockIdx.y;
    for (int i = tid; i < 512; i += 128) {
        ((float4*)Fr_s)[i] = ((const float4*)g_Fr)[i];
        ((float4*)Fi_s)[i] = ((const float4*)g_Fi)[i];
    }
    __syncthreads();
    float xr[8], xi[8];
#pragma unroll
    for (int k = 0; k < 8; k++) { xr[k] = 0.f; xi[k] = 0.f; }
    const float* Yr = g_Y2 + (size_t)(b * 32 + 2 * k1) * 8192 + c;
    const float* Yi = Yr + 8192;
#pragma unroll 2
    for (int w = 0; w < 128; w++) {
        float vr = Yr[w * 64];
        float vi = Yi[w * 64];
        float4 fra = *(const float4*)(Fr_s + w * 16 + k2h * 8);
        float4 frb = *(const float4*)(Fr_s + w * 16 + k2h * 8 + 4);
        float4 fia = *(const float4*)(Fi_s + w * 16 + k2h * 8);
        float4 fib = *(const float4*)(Fi_s + w * 16 + k2h * 8 + 4);
        const float* fr = (const float*)&fra;
        const float* fi = (const float*)&fia;
#pragma unroll
        for (int k = 0; k < 4; k++) {
            xr[k] += fr[k] * vr - fi[k] * vi;
            xi[k] += fr[k] * vi + fi[k] * vr;
        }
        const float* fr2 = (const float*)&frb;
        const float* fi2 = (const float*)&fib;
#pragma unroll
        for (int k = 0; k < 4; k++) {
            xr[4 + k] += fr2[k] * vr - fi2[k] * vi;
            xi[4 + k] += fr2[k] * vi + fi2[k] * vr;
        }
    }
    float* dst = g_X2 + (size_t)(b * 16 + k1) * 2048;
#pragma unroll
    for (int k = 0; k < 8; k++) {
        dst[(k2h * 8 + k) * 64 + c]        = xr[k];
        dst[1024 + (k2h * 8 + k) * 64 + c] = xi[k];
    }
}

// ---------------------------------------------------------------------------
// Spectral einsum GEMM (tf32 mma, split-K, block-structured B):
//   O(256x2048) = X2(256x2048) * [[Wr, Wi], [-Wi, Wr]]
// grid (32 n, 2 m, 8 kz), 128 threads. BM=128, BN=64, Kchunk=256.
__global__ void __launch_bounds__(128) gemm_mma(int layer) {
    int tid = threadIdx.x, warp = tid >> 5, lane = tid & 31;
    int gid = lane >> 2, tig = lane & 3;
    int cBase = blockIdx.x * 64;
    int rBase = blockIdx.y * 128 + warp * 32;
    int kz = blockIdx.z;
    bool kTop = kz < 4;
    bool cTop = cBase < 1024;
    const float* Bbase;
    float sgn = 1.f;
    if (kTop) Bbase = cTop ? g_Wr : g_Wi;
    else { Bbase = cTop ? g_Wi : g_Wr; if (cTop) sgn = -1.f; }
    Bbase += (size_t)layer * 1048576 + (size_t)((kz & 3) * 256) * 1024 + (cBase & 1023);

    float acc[2][8][4];
#pragma unroll
    for (int m = 0; m < 2; m++)
#pragma unroll
        for (int n = 0; n < 8; n++)
#pragma unroll
            for (int j = 0; j < 4; j++) acc[m][n][j] = 0.f;

    for (int ks = 0; ks < 32; ks++) {
        int k0 = ks * 8;
        const float* Bp = Bbase + (size_t)(k0 + tig) * 1024 + gid;
        unsigned bf[8][2];
#pragma unroll
        for (int n = 0; n < 8; n++) {
            bf[n][0] = f2tf(sgn * Bp[n * 8]);
            bf[n][1] = f2tf(sgn * Bp[4 * 1024 + n * 8]);
        }
#pragma unroll
        for (int m = 0; m < 2; m++) {
            const float* Ap = g_X2 + (size_t)(rBase + m * 16 + gid) * 2048
                              + kz * 256 + k0 + tig;
            unsigned a0 = f2tf(Ap[0]);
            unsigned a1 = f2tf(Ap[8 * 2048]);
            unsigned a2 = f2tf(Ap[4]);
            unsigned a3 = f2tf(Ap[8 * 2048 + 4]);
#pragma unroll
            for (int n = 0; n < 8; n++)
                mma_tf32(acc[m][n], a0, a1, a2, a3, bf[n][0], bf[n][1]);
        }
    }
    __shared__ float Cs[128][68];
#pragma unroll
    for (int m = 0; m < 2; m++)
#pragma unroll
        for (int n = 0; n < 8; n++) {
            int rl = warp * 32 + m * 16 + gid;
            int cl = n * 8 + 2 * tig;
            Cs[rl][cl]         = acc[m][n][0];
            Cs[rl][cl + 1]     = acc[m][n][1];
            Cs[rl + 8][cl]     = acc[m][n][2];
            Cs[rl + 8][cl + 1] = acc[m][n][3];
        }
    __syncthreads();
    float* dst = g_Op + (size_t)kz * 524288
               + (size_t)(blockIdx.y * 128) * 2048 + cBase;
    for (int i4 = tid; i4 < 2048; i4 += 128) {
        int row = i4 >> 4, c4 = (i4 & 15) * 4;
        *(float4*)(dst + (size_t)row * 2048 + c4) = *(float4*)&Cs[row][c4];
    }
}

// Sum 8 split-K partials.  grid 512 x 256 (float4).
__global__ void reduceO_kernel() {
    int i4 = blockIdx.x * 256 + threadIdx.x;     // < 131072
    float4 a = ((const float4*)g_Op)[i4];
#pragma unroll
    for (int s = 1; s < 8; s++) {
        float4 b = ((const float4*)g_Op)[s * 131072 + i4];
        a.x += b.x; a.y += b.y; a.z += b.z; a.w += b.w;
    }
    ((float4*)g_O)[i4] = a;
}

// ---------------------------------------------------------------------------
// Stage C: inverse DFT over H-modes (K=16); emits TT layout for stageD mma:
//   TT[b*128+h][2m] = Tr, TT[..][2m+1] = -Ti.
__global__ void stageC_kernel() {
    int i = blockIdx.x * 256 + threadIdx.x;           // 2,097,152
    int o  = i & 63;
    int m  = (i >> 6) & 15;
    int hh = (i >> 10) & 127;
    int b  = i >> 17;
    const float* Gr = g_Gr + hh * 16;
    const float* Gi = g_Gi + hh * 16;
    const float* Op = g_O + (size_t)b * 16 * 2048 + m * 64 + o;
    float tr = 0.f, ti = 0.f;
#pragma unroll
    for (int x = 0; x < 16; x++) {
        float gr = Gr[x], gi = Gi[x];
        float orr = Op[(size_t)x * 2048];
        float oii = Op[(size_t)x * 2048 + 1024];
        tr += gr * orr - gi * oii;
        ti += gr * oii + gi * orr;
    }
    size_t base = ((size_t)(b * 128 + hh) * 32 + 2 * m) * 64 + o;
    g_TT[base]      = tr;
    g_TT[base + 64] = -ti;
}

// ---------------------------------------------------------------------------
// Stage D (mma, fused): per (b,h) row:
//   C(128x64) = [G2(128x32) | hrow(128x64)] x [TT(32x64); ww(64x64)]
//   h = gelu(C + wb)   (in-place)
// grid (128 h, 16 b), 128 threads.
__global__ void __launch_bounds__(128) stageD_mma(const float* __restrict__ ww,
                                                  const float* __restrict__ wb) {
    int tid = threadIdx.x, warp = tid >> 5, lane = tid & 31;
    int gid = lane >> 2, tig = lane & 3;
    int hh = blockIdx.x, b = blockIdx.y;
    size_t rowbase = (size_t)(b * 128 + hh) * 8192;
    const float* TT = g_TT + (size_t)(b * 128 + hh) * 2048;
    int m0 = warp * 32;

    float acc[2][8][4];
#pragma unroll
    for (int m = 0; m < 2; m++)
#pragma unroll
        for (int n = 0; n < 8; n++)
#pragma unroll
            for (int j = 0; j < 4; j++) acc[m][n][j] = 0.f;

#pragma unroll
    for (int ks = 0; ks < 12; ks++) {
        int k0 = ks * 8;
        const float* Bp = (k0 < 32) ? (TT + (k0 + tig) * 64)
                                    : (ww + (k0 - 32 + tig) * 64);
        unsigned bf[8][2];
#pragma unroll
        for (int n = 0; n < 8; n++) {
            bf[n][0] = f2tf(Bp[n * 8 + gid]);
            bf[n][1] = f2tf(Bp[4 * 64 + n * 8 + gid]);
        }
#pragma unroll
        for (int m = 0; m < 2; m++) {
            int w = m0 + m * 16 + gid;
            unsigned a0, a1, a2, a3;
            if (k0 < 32) {
                a0 = f2tf(g_G2[w * 32 + k0 + tig]);
                a1 = f2tf(g_G2[(w + 8) * 32 + k0 + tig]);
                a2 = f2tf(g_G2[w * 32 + k0 + tig + 4]);
                a3 = f2tf(g_G2[(w + 8) * 32 + k0 + tig + 4]);
            } else {
                const float* hp = g_h + rowbase + (size_t)w * 64 + (k0 - 32) + tig;
                a0 = f2tf(hp[0]);
                a1 = f2tf(hp[8 * 64]);
                a2 = f2tf(hp[4]);
                a3 = f2tf(hp[8 * 64 + 4]);
            }
#pragma unroll
            for (int n = 0; n < 8; n++)
                mma_tf32(acc[m][n], a0, a1, a2, a3, bf[n][0], bf[n][1]);
        }
    }
    __shared__ float Cs[128][68];
#pragma unroll
    for (int m = 0; m < 2; m++)
#pragma unroll
        for (int n = 0; n < 8; n++) {
            int rl = m0 + m * 16 + gid;
            int cl = n * 8 + 2 * tig;
            float wb0 = wb[cl], wb1 = wb[cl + 1];
            Cs[rl][cl]         = gelu_f(acc[m][n][0] + wb0);
            Cs[rl][cl + 1]     = gelu_f(acc[m][n][1] + wb1);
            Cs[rl + 8][cl]     = gelu_f(acc[m][n][2] + wb0);
            Cs[rl + 8][cl + 1] = gelu_f(acc[m][n][3] + wb1);
        }
    __syncthreads();
    for (int i4 = tid; i4 < 2048; i4 += 128) {
        int row = i4 >> 4, c4 = (i4 & 15) * 4;
        *(float4*)(g_h + rowbase + (size_t)row * 64 + c4) = *(float4*)&Cs[row][c4];
    }
}

// ---------------------------------------------------------------------------
// Fused head (mma): out = gelu(h @ w1 + b1) @ w2 + b2.
// CTA: 256 threads (8 warps), 128 pixels; per warp M=16, N=128, K=64.
__global__ void __launch_bounds__(256) fc12_mma(const float* __restrict__ w1,
                                                const float* __restrict__ b1,
                                                const float* __restrict__ w2,
                                                const float* __restrict__ b2,
                                                float* __restrict__ out) {
    int tid = threadIdx.x, warp = tid >> 5, lane = tid & 31;
    int gid = lane >> 2, tig = lane & 3;
    size_t p0 = (size_t)blockIdx.x * 128;
    int m0 = warp * 16;

    float acc[16][4];
#pragma unroll
    for (int n = 0; n < 16; n++)
#pragma unroll
        for (int j = 0; j < 4; j++) acc[n][j] = 0.f;

#pragma unroll
    for (int ks = 0; ks < 8; ks++) {
        int k0 = ks * 8;
        const float* Bp = w1 + (k0 + tig) * 128 + gid;
        unsigned bf[16][2];
#pragma unroll
        for (int n = 0; n < 16; n++) {
            bf[n][0] = f2tf(Bp[n * 8]);
            bf[n][1] = f2tf(Bp[4 * 128 + n * 8]);
        }
        const float* hp = g_h + (p0 + m0 + gid) * 64 + k0 + tig;
        unsigned a0 = f2tf(hp[0]);
        unsigned a1 = f2tf(hp[8 * 64]);
        unsigned a2 = f2tf(hp[4]);
        unsigned a3 = f2tf(hp[8 * 64 + 4]);
#pragma unroll
        for (int n = 0; n < 16; n++)
            mma_tf32(acc[n], a0, a1, a2, a3, bf[n][0], bf[n][1]);
    }
    float s0 = 0.f, s1 = 0.f;
#pragma unroll
    for (int n = 0; n < 16; n++) {
        int col = n * 8 + 2 * tig;
        float w2a = w2[col], w2b = w2[col + 1];
        float b1a = b1[col], b1b = b1[col + 1];
        s0 += gelu_f(acc[n][0] + b1a) * w2a + gelu_f(acc[n][1] + b1b) * w2b;
        s1 += gelu_f(acc[n][2] + b1a) * w2a + gelu_f(acc[n][3] + b1b) * w2b;
    }
    s0 += __shfl_xor_sync(0xffffffffu, s0, 1);
    s0 += __shfl_xor_sync(0xffffffffu, s0, 2);
    s1 += __shfl_xor_sync(0xffffffffu, s1, 1);
    s1 += __shfl_xor_sync(0xffffffffu, s1, 2);
    if (tig == 0) {
        float bb = b2[0];
        out[p0 + m0 + gid]     = s0 + bb;
        out[p0 + m0 + gid + 8] = s1 + bb;
    }
}

// ---------------------------------------------------------------------------
extern "C" void kernel_launch(void* const* d_in, const int* in_sizes, int n_in,
                              void* d_out, int out_size) {
    const float* x       = (const float*)d_in[0];
    const float* fc_in_w = (const float*)d_in[1];
    const float* fc_in_b = (const float*)d_in[2];
    const float* wr      = (const float*)d_in[3];
    const float* wi      = (const float*)d_in[4];
    const float* ww      = (const float*)d_in[5];
    const float* wb      = (const float*)d_in[6];
    const float* fc1_w   = (const float*)d_in[7];
    const float* fc1_b   = (const float*)d_in[8];
    const float* fc2_w   = (const float*)d_in[9];
    const float* fc2_b   = (const float*)d_in[10];
    float* out = (float*)d_out;

    twiddle_kernel<<<8, 256>>>();
    presum_kernel<<<16384, 256>>>(wr, wi);
    fcin_kernel<<<65536, 256>>>(x, fc_in_w, fc_in_b);

    for (int l = 0; l < 4; l++) {
        stageA_mma<<<dim3(32, 16), 128>>>();
        stageB_kernel<<<dim3(16, 16), 128>>>();
        gemm_mma<<<dim3(32, 2, 8), 128>>>(l);
        reduceO_kernel<<<512, 256>>>();
        stageC_kernel<<<8192, 256>>>();
        stageD_mma<<<dim3(128, 16), 128>>>(ww + (size_t)l * 4096,
                                           wb + (size_t)l * 64);
    }
    fc12_mma<<<2048, 256>>>(fc1_w, fc1_b, fc2_w, fc2_b, out);
}